// round 2
// baseline (speedup 1.0000x reference)
#include <cuda_runtime.h>
#include <cstdint>
#include <float.h>

#define NB    4
#define NPTS  8192
#define NPQ   2048
#define NCH   128

// ---------------- device scratch (statically allocated; no cudaMalloc) ----------------
__device__ float4 g_p4[NB * NPTS];                    // (x,y,z,|p|^2)
__device__ float4 g_q4[NB * NPQ];                     // sampled points
__device__ int    g_fps[NB * NPQ];
__device__ float  g_feat_t[(size_t)NB * NPTS * NCH];  // features transposed [B,N,C]
__device__ float  g_coarse_t[(size_t)NB * NPQ * NCH]; // pooled features [B,q,C]
__device__ int    g_i3[NB * NPTS * 3];
__device__ float  g_w3[NB * NPTS * 3];

typedef unsigned long long u64;

// ---------------- packed f32x2 helpers ----------------
__device__ __forceinline__ u64 pk2(float a, float b) {
    u64 r; asm("mov.b64 %0, {%1,%2};" : "=l"(r) : "f"(a), "f"(b)); return r;
}
__device__ __forceinline__ void upk2(u64 v, float& a, float& b) {
    asm("mov.b64 {%0,%1}, %2;" : "=f"(a), "=f"(b) : "l"(v));
}
__device__ __forceinline__ u64 add2(u64 a, u64 b) {
    u64 r; asm("add.rn.f32x2 %0, %1, %2;" : "=l"(r) : "l"(a), "l"(b)); return r;
}
__device__ __forceinline__ u64 mul2(u64 a, u64 b) {
    u64 r; asm("mul.rn.f32x2 %0, %1, %2;" : "=l"(r) : "l"(a), "l"(b)); return r;
}
__device__ __forceinline__ u64 fma2(u64 a, u64 b, u64 c) {
    u64 r; asm("fma.rn.f32x2 %0, %1, %2, %3;" : "=l"(r) : "l"(a), "l"(b), "l"(c)); return r;
}

// ---------------- prep: pack points + squared norm ----------------
__global__ void prep_kernel(const float* __restrict__ pts) {
    int i = blockIdx.x * 256 + threadIdx.x;          // over NB*NPTS
    float x = pts[3 * i], y = pts[3 * i + 1], z = pts[3 * i + 2];
    float nr = __fmaf_rn(z, z, __fmaf_rn(y, y, x * x));
    g_p4[i] = make_float4(x, y, z, nr);
}

// ---------------- transpose features [B,C,N] -> [B,N,C] ----------------
__global__ void transpose_kernel(const float* __restrict__ f) {
    __shared__ float tile[32][33];
    int b = blockIdx.z;
    int c0 = blockIdx.y * 32, n0 = blockIdx.x * 32;
    tile[threadIdx.y][threadIdx.x] =
        f[((size_t)b * NCH + c0 + threadIdx.y) * NPTS + n0 + threadIdx.x];
    __syncthreads();
    g_feat_t[((size_t)b * NPTS + n0 + threadIdx.y) * NCH + c0 + threadIdx.x] =
        tile[threadIdx.x][threadIdx.y];
}

// ---------------- FPS: one CTA per batch, 1024 threads, 8 pts/thread ----------------
// Atomic-free reduction: per-warp max -> smem (plain store) -> every warp
// redundantly shuffle-reduces the 32 warp maxima (no second barrier, no
// single-warp bottleneck, no serialized smem atomics). Argmax via equality
// scan + atomicMin (fires ~1 thread/iter) -> lowest index = jnp.argmax tie rule.
__global__ void __launch_bounds__(1024, 1) fps_kernel() {
    const int b    = blockIdx.x;
    const int tid  = threadIdx.x;
    const int lane = tid & 31;
    const int wid  = tid >> 5;
    const float4* __restrict__ P = g_p4 + b * NPTS;

    // pair i holds points  n = i*2048 + tid*2 + {0,1}  (coalesced 32B/thread loads)
    u64 X[4], Y[4], Z[4];
    float dist[8];
#pragma unroll
    for (int i = 0; i < 4; i++) {
        int n0 = i * 2048 + tid * 2;
        float4 a = P[n0];
        float4 c = P[n0 + 1];
        X[i] = pk2(a.x, c.x); Y[i] = pk2(a.y, c.y); Z[i] = pk2(a.z, c.z);
    }

    __shared__ float swarp[32];
    __shared__ int   sidx[2];
    if (tid == 0) {
        sidx[0] = 0x7fffffff; sidx[1] = 0x7fffffff;
        g_fps[b * NPQ] = 0;
    }

    // d0 = ||x - x0||^2  (same fma chain as reference)
    float4 q0 = P[0];
    u64 nqx = pk2(-q0.x, -q0.x), nqy = pk2(-q0.y, -q0.y), nqz = pk2(-q0.z, -q0.z);
    float bv = 0.f;
#pragma unroll
    for (int i = 0; i < 4; i++) {
        u64 dx = add2(X[i], nqx), dy = add2(Y[i], nqy), dz = add2(Z[i], nqz);
        u64 t = fma2(dz, dz, fma2(dy, dy, mul2(dx, dx)));
        float a, c; upk2(t, a, c);
        dist[2 * i] = a; dist[2 * i + 1] = c;
        bv = fmaxf(bv, fmaxf(a, c));
    }
    // per-warp max -> smem
#pragma unroll
    for (int s = 16; s > 0; s >>= 1)
        bv = fmaxf(bv, __shfl_xor_sync(0xffffffffu, bv, s));
    if (lane == 0) swarp[wid] = bv;

    const int t2 = tid * 2;

    for (int j = 1; j < NPQ; j++) {
        __syncthreads();                       // swarp[] of prev iter visible
        // every warp redundantly reduces the 32 per-warp maxima
        float gmax = swarp[lane];
#pragma unroll
        for (int s = 16; s > 0; s >>= 1)
            gmax = fmaxf(gmax, __shfl_xor_sync(0xffffffffu, gmax, s));

        int slot = j & 1;
        // equality scan; atomicMin -> lowest index (matches jnp.argmax first-occurrence)
#pragma unroll
        for (int k = 0; k < 8; k++) {
            if (dist[k] == gmax)
                atomicMin(&sidx[slot], t2 + (k >> 1) * 2048 + (k & 1));
        }
        if (tid == 0) sidx[slot ^ 1] = 0x7fffffff;  // reset other slot for next iter
        __syncthreads();                       // sidx[slot] final

        int nxt = sidx[slot];
        if (tid == 0) g_fps[b * NPQ + j] = nxt;

        float4 qq = P[nxt];   // broadcast load (L1-hit)
        u64 ax = pk2(-qq.x, -qq.x), ay = pk2(-qq.y, -qq.y), az = pk2(-qq.z, -qq.z);
        bv = 0.f;
#pragma unroll
        for (int i = 0; i < 4; i++) {
            u64 dx = add2(X[i], ax), dy = add2(Y[i], ay), dz = add2(Z[i], az);
            u64 t = fma2(dz, dz, fma2(dy, dy, mul2(dx, dx)));
            float a, c; upk2(t, a, c);
            float m0 = fminf(dist[2 * i], a);
            float m1 = fminf(dist[2 * i + 1], c);
            dist[2 * i] = m0; dist[2 * i + 1] = m1;
            bv = fmaxf(bv, fmaxf(m0, m1));
        }
        // per-warp max -> smem (plain store; visibility via next iter's barrier)
#pragma unroll
        for (int s = 16; s > 0; s >>= 1)
            bv = fmaxf(bv, __shfl_xor_sync(0xffffffffu, bv, s));
        if (lane == 0) swarp[wid] = bv;
    }
}

// ---------------- gather sampled coords ----------------
__global__ void gather_q4_kernel() {
    int i = blockIdx.x * 256 + threadIdx.x;          // over NB*NPQ
    int b = i >> 11;
    g_q4[i] = g_p4[b * NPTS + g_fps[i]];
}

// ---------------- kNN (top-17 smallest, drop nearest) + mean-pool features ----------------
__global__ void __launch_bounds__(256) knn_group_kernel() {
    int gw   = blockIdx.x * 8 + (threadIdx.x >> 5);  // global query id = b*NPQ + qi
    int lane = threadIdx.x & 31;
    int b    = gw >> 11;

    float4 q = g_q4[gw];
    const float4* __restrict__ P = g_p4 + b * NPTS;

    float d[17]; int id[17];
#pragma unroll
    for (int t = 0; t < 17; t++) { d[t] = FLT_MAX; id[t] = 0x7fffffff; }

    // lane-local sorted top-17 over 256 strided candidates
    for (int t = 0; t < NPTS / 32; t++) {
        int n = t * 32 + lane;
        float4 p = P[n];
        float dot = __fmaf_rn(q.z, p.z, __fmaf_rn(q.y, p.y, q.x * p.x));
        float sq  = fmaxf(__fmaf_rn(-2.f, dot, q.w + p.w), 0.f);
        if (sq < d[16]) {
            d[16] = sq; id[16] = n;
#pragma unroll
            for (int jj = 16; jj > 0; jj--) {
                if (d[jj] < d[jj - 1]) {
                    float td = d[jj]; d[jj] = d[jj - 1]; d[jj - 1] = td;
                    int   ti = id[jj]; id[jj] = id[jj - 1]; id[jj - 1] = ti;
                }
            }
        }
    }

    // 17-round k-way merge across lanes; skip round 0 (self/nearest), accumulate 16 nbrs
    float4 acc = make_float4(0.f, 0.f, 0.f, 0.f);
    const float* Fb = g_feat_t + (size_t)b * NPTS * NCH;
    u64 key = ((u64)__float_as_uint(d[0]) << 32) | (unsigned)id[0];
    for (int r = 0; r < 17; r++) {
        u64 m = key;
#pragma unroll
        for (int s = 16; s > 0; s >>= 1) {
            u64 o = __shfl_xor_sync(0xffffffffu, m, s);
            m = (o < m) ? o : m;
        }
        if (r > 0) {
            int nn = (int)(unsigned)m;
            const float4* row = (const float4*)(Fb + (size_t)nn * NCH);
            float4 f = row[lane];
            acc.x += f.x; acc.y += f.y; acc.z += f.z; acc.w += f.w;
        }
        if (key == m) {
#pragma unroll
            for (int jj = 0; jj < 16; jj++) { d[jj] = d[jj + 1]; id[jj] = id[jj + 1]; }
            d[16] = FLT_MAX; id[16] = 0x7fffffff;
        }
        key = ((u64)__float_as_uint(d[0]) << 32) | (unsigned)id[0];
    }

    float4 o = make_float4(acc.x * 0.0625f, acc.y * 0.0625f,
                           acc.z * 0.0625f, acc.w * 0.0625f);
    ((float4*)(g_coarse_t + (size_t)gw * NCH))[lane] = o;
}

// ---------------- three_nn: 3 nearest sampled points + inverse-distance weights ----------------
__global__ void __launch_bounds__(256) three_nn_kernel() {
    int b = blockIdx.y;
    int n = blockIdx.x * 256 + threadIdx.x;
    __shared__ float4 sq4[NPQ];
    for (int i = threadIdx.x; i < NPQ; i += 256) sq4[i] = g_q4[b * NPQ + i];
    __syncthreads();

    float4 p = g_p4[b * NPTS + n];
    float d0 = FLT_MAX, d1 = FLT_MAX, d2 = FLT_MAX;
    int   i0 = 0, i1 = 0, i2 = 0;
    for (int j = 0; j < NPQ; j++) {
        float4 q = sq4[j];
        float dot = __fmaf_rn(q.z, p.z, __fmaf_rn(q.y, p.y, q.x * p.x));
        float s   = fmaxf(__fmaf_rn(-2.f, dot, q.w + p.w), 0.f);
        bool c2 = s < d2, c1 = s < d1, c0 = s < d0;
        d2 = c1 ? d1 : (c2 ? s : d2);
        i2 = c1 ? i1 : (c2 ? j : i2);
        d1 = c0 ? d0 : (c1 ? s : d1);
        i1 = c0 ? i0 : (c1 ? j : i1);
        d0 = c0 ? s : d0;
        i0 = c0 ? j : i0;
    }
    d0 = fmaxf(d0, 1e-10f); d1 = fmaxf(d1, 1e-10f); d2 = fmaxf(d2, 1e-10f);
    float v0 = __fdiv_rn(1.f, d0 + 1e-8f);
    float v1 = __fdiv_rn(1.f, d1 + 1e-8f);
    float v2 = __fdiv_rn(1.f, d2 + 1e-8f);
    float ss = v0 + v1 + v2;
    int o = (b * NPTS + n) * 3;
    g_i3[o] = i0; g_i3[o + 1] = i1; g_i3[o + 2] = i2;
    g_w3[o]     = __fdiv_rn(v0, ss);
    g_w3[o + 1] = __fdiv_rn(v1, ss);
    g_w3[o + 2] = __fdiv_rn(v2, ss);
}

// ---------------- interpolate: out[b,c,n] = sum_k w_k * coarse[b, i3_k, c] ----------------
__global__ void __launch_bounds__(256) interp_kernel(float* __restrict__ out) {
    int b    = blockIdx.y;
    int n    = blockIdx.x * 8 + threadIdx.y;
    int lane = threadIdx.x;                           // float4-channel index
    int o = (b * NPTS + n) * 3;
    int a0 = g_i3[o], a1 = g_i3[o + 1], a2 = g_i3[o + 2];
    float w0 = g_w3[o], w1 = g_w3[o + 1], w2 = g_w3[o + 2];

    const float4* C = (const float4*)g_coarse_t + (size_t)b * NPQ * (NCH / 4);
    float4 f0 = C[a0 * (NCH / 4) + lane];
    float4 f1 = C[a1 * (NCH / 4) + lane];
    float4 f2 = C[a2 * (NCH / 4) + lane];

    float4 r;
    r.x = __fmaf_rn(f2.x, w2, __fmaf_rn(f1.x, w1, f0.x * w0));
    r.y = __fmaf_rn(f2.y, w2, __fmaf_rn(f1.y, w1, f0.y * w0));
    r.z = __fmaf_rn(f2.z, w2, __fmaf_rn(f1.z, w1, f0.z * w0));
    r.w = __fmaf_rn(f2.w, w2, __fmaf_rn(f1.w, w1, f0.w * w0));

    float* op = out + (size_t)b * NCH * NPTS + n;
    int c = lane * 4;
    op[(size_t)(c + 0) * NPTS] = r.x;
    op[(size_t)(c + 1) * NPTS] = r.y;
    op[(size_t)(c + 2) * NPTS] = r.z;
    op[(size_t)(c + 3) * NPTS] = r.w;
}

// ---------------- launch ----------------
extern "C" void kernel_launch(void* const* d_in, const int* in_sizes, int n_in,
                              void* d_out, int out_size) {
    const float* points   = (const float*)d_in[0];
    const float* features = (const float*)d_in[1];
    for (int i = 0; i < n_in; i++) {
        if (in_sizes[i] == NB * NPTS * 3)            points   = (const float*)d_in[i];
        else if (in_sizes[i] == NB * NCH * NPTS)     features = (const float*)d_in[i];
    }
    float* out = (float*)d_out;

    prep_kernel<<<(NB * NPTS) / 256, 256>>>(points);
    transpose_kernel<<<dim3(NPTS / 32, NCH / 32, NB), dim3(32, 32)>>>(features);
    fps_kernel<<<NB, 1024>>>();
    gather_q4_kernel<<<(NB * NPQ) / 256, 256>>>();
    knn_group_kernel<<<(NB * NPQ) / 8, 256>>>();
    three_nn_kernel<<<dim3(NPTS / 256, NB), 256>>>();
    interp_kernel<<<dim3(NPTS / 8, NB), dim3(32, 8)>>>(out);
}

// round 3
// speedup vs baseline: 1.4046x; 1.4046x over previous
#include <cuda_runtime.h>
#include <cstdint>
#include <float.h>

#define NB    4
#define NPTS  8192
#define NPQ   2048
#define NCH   128

// ---------------- device scratch (statically allocated; no cudaMalloc) ----------------
__device__ float4 g_p4[NB * NPTS];                    // (x,y,z,|p|^2)
__device__ float4 g_q4[NB * NPQ];                     // sampled points
__device__ int    g_fps[NB * NPQ];
__device__ float  g_feat_t[(size_t)NB * NPTS * NCH];  // features transposed [B,N,C]
__device__ float  g_coarse_t[(size_t)NB * NPQ * NCH]; // pooled features [B,q,C]
__device__ int    g_i3[NB * NPTS * 3];
__device__ float  g_w3[NB * NPTS * 3];

typedef unsigned long long u64;

// ---------------- packed f32x2 helpers ----------------
__device__ __forceinline__ u64 pk2(float a, float b) {
    u64 r; asm("mov.b64 %0, {%1,%2};" : "=l"(r) : "f"(a), "f"(b)); return r;
}
__device__ __forceinline__ void upk2(u64 v, float& a, float& b) {
    asm("mov.b64 {%0,%1}, %2;" : "=f"(a), "=f"(b) : "l"(v));
}
__device__ __forceinline__ u64 add2(u64 a, u64 b) {
    u64 r; asm("add.rn.f32x2 %0, %1, %2;" : "=l"(r) : "l"(a), "l"(b)); return r;
}
__device__ __forceinline__ u64 mul2(u64 a, u64 b) {
    u64 r; asm("mul.rn.f32x2 %0, %1, %2;" : "=l"(r) : "l"(a), "l"(b)); return r;
}
__device__ __forceinline__ u64 fma2(u64 a, u64 b, u64 c) {
    u64 r; asm("fma.rn.f32x2 %0, %1, %2, %3;" : "=l"(r) : "l"(a), "l"(b), "l"(c)); return r;
}

// ---------------- prep: pack points + squared norm ----------------
__global__ void prep_kernel(const float* __restrict__ pts) {
    int i = blockIdx.x * 256 + threadIdx.x;          // over NB*NPTS
    float x = pts[3 * i], y = pts[3 * i + 1], z = pts[3 * i + 2];
    float nr = __fmaf_rn(z, z, __fmaf_rn(y, y, x * x));
    g_p4[i] = make_float4(x, y, z, nr);
}

// ---------------- transpose features [B,C,N] -> [B,N,C] ----------------
__global__ void transpose_kernel(const float* __restrict__ f) {
    __shared__ float tile[32][33];
    int b = blockIdx.z;
    int c0 = blockIdx.y * 32, n0 = blockIdx.x * 32;
    tile[threadIdx.y][threadIdx.x] =
        f[((size_t)b * NCH + c0 + threadIdx.y) * NPTS + n0 + threadIdx.x];
    __syncthreads();
    g_feat_t[((size_t)b * NPTS + n0 + threadIdx.y) * NCH + c0 + threadIdx.x] =
        tile[threadIdx.x][threadIdx.y];
}

// ---------------- FPS: one CTA per batch, 1024 threads, 8 pts/thread ----------------
// Single barrier per iteration. Hardware REDUX.SYNC warp reductions on
// distance float-bits (dist >= 0 -> u32-monotone). Argmax tie rule = lowest
// index everywhere (local strict-> tree, redux_min over tied candidates),
// matching jnp.argmax first-occurrence. Per-warp (distbits,idx) keys go to
// a parity double-buffered smem slot; every warp redundantly reduces the 32
// keys, so all threads learn nxt with no broadcast round-trip.
__global__ void __launch_bounds__(1024, 1) fps_kernel() {
    const int b    = blockIdx.x;
    const int tid  = threadIdx.x;
    const int lane = tid & 31;
    const int wid  = tid >> 5;
    const float4* __restrict__ P = g_p4 + b * NPTS;

    // pair i holds points  n = i*2048 + tid*2 + {0,1}  (coalesced 32B/thread loads)
    u64 X[4], Y[4], Z[4];
    float dist[8];
#pragma unroll
    for (int i = 0; i < 4; i++) {
        int n0 = i * 2048 + tid * 2;
        float4 a = P[n0];
        float4 c = P[n0 + 1];
        X[i] = pk2(a.x, c.x); Y[i] = pk2(a.y, c.y); Z[i] = pk2(a.z, c.z);
    }

    __shared__ u64 skey[2][32];
    const int t2 = tid * 2;
    if (tid == 0) g_fps[b * NPQ] = 0;

    // d0 = ||x - x0||^2  (same fma chain as reference)
    float4 q0 = P[0];
    {
        u64 ax = pk2(-q0.x, -q0.x), ay = pk2(-q0.y, -q0.y), az = pk2(-q0.z, -q0.z);
#pragma unroll
        for (int i = 0; i < 4; i++) {
            u64 dx = add2(X[i], ax), dy = add2(Y[i], ay), dz = add2(Z[i], az);
            u64 t = fma2(dz, dz, fma2(dy, dy, mul2(dx, dx)));
            upk2(t, dist[2 * i], dist[2 * i + 1]);
        }
        // local argmax tree (strict > keeps lowest k = lowest index on ties)
        float m01 = dist[0]; int k01 = 0; if (dist[1] > m01) { m01 = dist[1]; k01 = 1; }
        float m23 = dist[2]; int k23 = 2; if (dist[3] > m23) { m23 = dist[3]; k23 = 3; }
        float m45 = dist[4]; int k45 = 4; if (dist[5] > m45) { m45 = dist[5]; k45 = 5; }
        float m67 = dist[6]; int k67 = 6; if (dist[7] > m67) { m67 = dist[7]; k67 = 7; }
        if (m23 > m01) { m01 = m23; k01 = k23; }
        if (m67 > m45) { m45 = m67; k45 = k67; }
        if (m45 > m01) { m01 = m45; k01 = k45; }
        unsigned bn = (unsigned)(((k01 >> 1) << 11) + t2 + (k01 & 1));
        unsigned db   = __float_as_uint(m01);
        unsigned wmax = __reduce_max_sync(0xffffffffu, db);
        unsigned cand = (db == wmax) ? bn : 0xffffffffu;
        unsigned widx = __reduce_min_sync(0xffffffffu, cand);
        if (lane == 0) skey[0][wid] = ((u64)wmax << 32) | widx;
    }

    for (int j = 1; j < NPQ; j++) {
        __syncthreads();                           // prev-iter skey visible
        u64 k64 = skey[(j - 1) & 1][lane];
        unsigned d32 = (unsigned)(k64 >> 32);
        unsigned i32 = (unsigned)k64;
        unsigned gmax = __reduce_max_sync(0xffffffffu, d32);
        unsigned c2   = (d32 == gmax) ? i32 : 0xffffffffu;
        unsigned nxt  = __reduce_min_sync(0xffffffffu, c2);
        if (tid == 0) g_fps[b * NPQ + j] = (int)nxt;

        float4 qq = P[nxt];                        // broadcast load (L1-hit)
        u64 ax = pk2(-qq.x, -qq.x), ay = pk2(-qq.y, -qq.y), az = pk2(-qq.z, -qq.z);
#pragma unroll
        for (int i = 0; i < 4; i++) {
            u64 dx = add2(X[i], ax), dy = add2(Y[i], ay), dz = add2(Z[i], az);
            u64 t = fma2(dz, dz, fma2(dy, dy, mul2(dx, dx)));
            float a, c; upk2(t, a, c);
            dist[2 * i]     = fminf(dist[2 * i], a);
            dist[2 * i + 1] = fminf(dist[2 * i + 1], c);
        }
        // local argmax tree
        float m01 = dist[0]; int k01 = 0; if (dist[1] > m01) { m01 = dist[1]; k01 = 1; }
        float m23 = dist[2]; int k23 = 2; if (dist[3] > m23) { m23 = dist[3]; k23 = 3; }
        float m45 = dist[4]; int k45 = 4; if (dist[5] > m45) { m45 = dist[5]; k45 = 5; }
        float m67 = dist[6]; int k67 = 6; if (dist[7] > m67) { m67 = dist[7]; k67 = 7; }
        if (m23 > m01) { m01 = m23; k01 = k23; }
        if (m67 > m45) { m45 = m67; k45 = k67; }
        if (m45 > m01) { m01 = m45; k01 = k45; }
        unsigned bn = (unsigned)(((k01 >> 1) << 11) + t2 + (k01 & 1));
        unsigned db   = __float_as_uint(m01);
        unsigned wmax = __reduce_max_sync(0xffffffffu, db);
        unsigned cand = (db == wmax) ? bn : 0xffffffffu;
        unsigned widx = __reduce_min_sync(0xffffffffu, cand);
        if (lane == 0) skey[j & 1][wid] = ((u64)wmax << 32) | widx;
    }
}

// ---------------- gather sampled coords ----------------
__global__ void gather_q4_kernel() {
    int i = blockIdx.x * 256 + threadIdx.x;          // over NB*NPQ
    int b = i >> 11;
    g_q4[i] = g_p4[b * NPTS + g_fps[i]];
}

// ---------------- kNN (top-17 smallest, drop nearest) + mean-pool features ----------------
__global__ void __launch_bounds__(256) knn_group_kernel() {
    int gw   = blockIdx.x * 8 + (threadIdx.x >> 5);  // global query id = b*NPQ + qi
    int lane = threadIdx.x & 31;
    int b    = gw >> 11;

    float4 q = g_q4[gw];
    const float4* __restrict__ P = g_p4 + b * NPTS;

    float d[17]; int id[17];
#pragma unroll
    for (int t = 0; t < 17; t++) { d[t] = FLT_MAX; id[t] = 0x7fffffff; }

    // lane-local sorted top-17 over 256 strided candidates
    for (int t = 0; t < NPTS / 32; t++) {
        int n = t * 32 + lane;
        float4 p = P[n];
        float dot = __fmaf_rn(q.z, p.z, __fmaf_rn(q.y, p.y, q.x * p.x));
        float sq  = fmaxf(__fmaf_rn(-2.f, dot, q.w + p.w), 0.f);
        if (sq < d[16]) {
            d[16] = sq; id[16] = n;
#pragma unroll
            for (int jj = 16; jj > 0; jj--) {
                if (d[jj] < d[jj - 1]) {
                    float td = d[jj]; d[jj] = d[jj - 1]; d[jj - 1] = td;
                    int   ti = id[jj]; id[jj] = id[jj - 1]; id[jj - 1] = ti;
                }
            }
        }
    }

    // 17-round k-way merge across lanes; skip round 0 (self/nearest), accumulate 16 nbrs
    float4 acc = make_float4(0.f, 0.f, 0.f, 0.f);
    const float* Fb = g_feat_t + (size_t)b * NPTS * NCH;
    u64 key = ((u64)__float_as_uint(d[0]) << 32) | (unsigned)id[0];
    for (int r = 0; r < 17; r++) {
        u64 m = key;
#pragma unroll
        for (int s = 16; s > 0; s >>= 1) {
            u64 o = __shfl_xor_sync(0xffffffffu, m, s);
            m = (o < m) ? o : m;
        }
        if (r > 0) {
            int nn = (int)(unsigned)m;
            const float4* row = (const float4*)(Fb + (size_t)nn * NCH);
            float4 f = row[lane];
            acc.x += f.x; acc.y += f.y; acc.z += f.z; acc.w += f.w;
        }
        if (key == m) {
#pragma unroll
            for (int jj = 0; jj < 16; jj++) { d[jj] = d[jj + 1]; id[jj] = id[jj + 1]; }
            d[16] = FLT_MAX; id[16] = 0x7fffffff;
        }
        key = ((u64)__float_as_uint(d[0]) << 32) | (unsigned)id[0];
    }

    float4 o = make_float4(acc.x * 0.0625f, acc.y * 0.0625f,
                           acc.z * 0.0625f, acc.w * 0.0625f);
    ((float4*)(g_coarse_t + (size_t)gw * NCH))[lane] = o;
}

// ---------------- three_nn: 3 nearest sampled points + inverse-distance weights ----------------
__global__ void __launch_bounds__(256) three_nn_kernel() {
    int b = blockIdx.y;
    int n = blockIdx.x * 256 + threadIdx.x;
    __shared__ float4 sq4[NPQ];
    for (int i = threadIdx.x; i < NPQ; i += 256) sq4[i] = g_q4[b * NPQ + i];
    __syncthreads();

    float4 p = g_p4[b * NPTS + n];
    float d0 = FLT_MAX, d1 = FLT_MAX, d2 = FLT_MAX;
    int   i0 = 0, i1 = 0, i2 = 0;
    for (int j = 0; j < NPQ; j++) {
        float4 q = sq4[j];
        float dot = __fmaf_rn(q.z, p.z, __fmaf_rn(q.y, p.y, q.x * p.x));
        float s   = fmaxf(__fmaf_rn(-2.f, dot, q.w + p.w), 0.f);
        bool c2 = s < d2, c1 = s < d1, c0 = s < d0;
        d2 = c1 ? d1 : (c2 ? s : d2);
        i2 = c1 ? i1 : (c2 ? j : i2);
        d1 = c0 ? d0 : (c1 ? s : d1);
        i1 = c0 ? i0 : (c1 ? j : i1);
        d0 = c0 ? s : d0;
        i0 = c0 ? j : i0;
    }
    d0 = fmaxf(d0, 1e-10f); d1 = fmaxf(d1, 1e-10f); d2 = fmaxf(d2, 1e-10f);
    float v0 = __fdiv_rn(1.f, d0 + 1e-8f);
    float v1 = __fdiv_rn(1.f, d1 + 1e-8f);
    float v2 = __fdiv_rn(1.f, d2 + 1e-8f);
    float ss = v0 + v1 + v2;
    int o = (b * NPTS + n) * 3;
    g_i3[o] = i0; g_i3[o + 1] = i1; g_i3[o + 2] = i2;
    g_w3[o]     = __fdiv_rn(v0, ss);
    g_w3[o + 1] = __fdiv_rn(v1, ss);
    g_w3[o + 2] = __fdiv_rn(v2, ss);
}

// ---------------- interpolate: out[b,c,n] = sum_k w_k * coarse[b, i3_k, c] ----------------
__global__ void __launch_bounds__(256) interp_kernel(float* __restrict__ out) {
    int b    = blockIdx.y;
    int n    = blockIdx.x * 8 + threadIdx.y;
    int lane = threadIdx.x;                           // float4-channel index
    int o = (b * NPTS + n) * 3;
    int a0 = g_i3[o], a1 = g_i3[o + 1], a2 = g_i3[o + 2];
    float w0 = g_w3[o], w1 = g_w3[o + 1], w2 = g_w3[o + 2];

    const float4* C = (const float4*)g_coarse_t + (size_t)b * NPQ * (NCH / 4);
    float4 f0 = C[a0 * (NCH / 4) + lane];
    float4 f1 = C[a1 * (NCH / 4) + lane];
    float4 f2 = C[a2 * (NCH / 4) + lane];

    float4 r;
    r.x = __fmaf_rn(f2.x, w2, __fmaf_rn(f1.x, w1, f0.x * w0));
    r.y = __fmaf_rn(f2.y, w2, __fmaf_rn(f1.y, w1, f0.y * w0));
    r.z = __fmaf_rn(f2.z, w2, __fmaf_rn(f1.z, w1, f0.z * w0));
    r.w = __fmaf_rn(f2.w, w2, __fmaf_rn(f1.w, w1, f0.w * w0));

    float* op = out + (size_t)b * NCH * NPTS + n;
    int c = lane * 4;
    op[(size_t)(c + 0) * NPTS] = r.x;
    op[(size_t)(c + 1) * NPTS] = r.y;
    op[(size_t)(c + 2) * NPTS] = r.z;
    op[(size_t)(c + 3) * NPTS] = r.w;
}

// ---------------- launch ----------------
extern "C" void kernel_launch(void* const* d_in, const int* in_sizes, int n_in,
                              void* d_out, int out_size) {
    const float* points   = (const float*)d_in[0];
    const float* features = (const float*)d_in[1];
    for (int i = 0; i < n_in; i++) {
        if (in_sizes[i] == NB * NPTS * 3)            points   = (const float*)d_in[i];
        else if (in_sizes[i] == NB * NCH * NPTS)     features = (const float*)d_in[i];
    }
    float* out = (float*)d_out;

    prep_kernel<<<(NB * NPTS) / 256, 256>>>(points);
    transpose_kernel<<<dim3(NPTS / 32, NCH / 32, NB), dim3(32, 32)>>>(features);
    fps_kernel<<<NB, 1024>>>();
    gather_q4_kernel<<<(NB * NPQ) / 256, 256>>>();
    knn_group_kernel<<<(NB * NPQ) / 8, 256>>>();
    three_nn_kernel<<<dim3(NPTS / 256, NB), 256>>>();
    interp_kernel<<<dim3(NPTS / 8, NB), dim3(32, 8)>>>(out);
}